// round 1
// baseline (speedup 1.0000x reference)
#include <cuda_runtime.h>
#include <cuda_bf16.h>

// Problem constants (fixed by the dataset)
#define N_Q   32768   // query points
#define M_R   16384   // reference points
#define KNN   8
#define SPLIT 4                 // split M across blocks for occupancy
#define MCHUNK (M_R / SPLIT)    // 4096 refs per chunk
#define TILE  2048              // refs per smem tile (32 KB of float4)
#define BQ    128               // queries (threads) per block

// Scratch (allocation-free rule: __device__ globals)
__device__ float4 g_refs[M_R];                     // (-2x, -2y, -2z, |r|^2)
__device__ float  g_part_d[SPLIT * N_Q * KNN];     // partial top-8 d' values
__device__ int    g_part_i[SPLIT * N_Q * KNN];     // partial top-8 indices

// ---------------------------------------------------------------------------
// Pack refs: p = (-2x, -2y, -2z, x^2+y^2+z^2) so that
//   d' = fma(p.x,qx, fma(p.y,qy, fma(p.z,qz, p.w))) = |r|^2 - 2 q.r
// and d^2 = d' + |q|^2 (per-query constant; irrelevant for ranking).
// ---------------------------------------------------------------------------
__global__ void prep_kernel(const float* __restrict__ ref) {
    int i = blockIdx.x * blockDim.x + threadIdx.x;
    if (i < M_R) {
        float x = ref[3 * i + 0];
        float y = ref[3 * i + 1];
        float z = ref[3 * i + 2];
        g_refs[i] = make_float4(-2.0f * x, -2.0f * y, -2.0f * z,
                                x * x + y * y + z * z);
    }
}

// Sorted-ascending 8-best insertion (b[7] is the current worst kept).
// Caller guarantees d < b[7]. Strict '<' in the bubble keeps earlier indices
// ahead on ties, matching jax.lax.top_k tie behavior.
__device__ __forceinline__ void insert8(float d, int id, float (&b)[KNN], int (&bi)[KNN]) {
    b[7] = d; bi[7] = id;
#pragma unroll
    for (int k = 7; k > 0; --k) {
        if (b[k] < b[k - 1]) {
            float t = b[k];  b[k] = b[k - 1];  b[k - 1] = t;
            int   u = bi[k]; bi[k] = bi[k - 1]; bi[k - 1] = u;
        }
    }
}

// ---------------------------------------------------------------------------
// Main KNN kernel: each thread owns one query; each block scans one M-chunk.
// Inner loop: 1 broadcast LDS.128 + 3 FFMA + 1 FSETP per ref.
// ---------------------------------------------------------------------------
__global__ __launch_bounds__(BQ) void knn_kernel(const float* __restrict__ q) {
    __shared__ float4 s_tile[TILE];

    const int qid   = blockIdx.x * BQ + threadIdx.x;
    const int chunk = blockIdx.y;
    const int base  = chunk * MCHUNK;

    const float qx = q[3 * qid + 0];
    const float qy = q[3 * qid + 1];
    const float qz = q[3 * qid + 2];

    float b[KNN];
    int   bi[KNN];
#pragma unroll
    for (int k = 0; k < KNN; ++k) { b[k] = __int_as_float(0x7f800000); bi[k] = 0; }

    for (int t = 0; t < MCHUNK; t += TILE) {
        // Cooperative tile load (L2-resident after first pass)
        for (int j = threadIdx.x; j < TILE; j += BQ)
            s_tile[j] = g_refs[base + t + j];
        __syncthreads();

#pragma unroll 4
        for (int j = 0; j < TILE; ++j) {
            float4 r = s_tile[j];  // broadcast: all lanes same address
            float d = fmaf(r.x, qx, fmaf(r.y, qy, fmaf(r.z, qz, r.w)));
            if (d < b[7]) insert8(d, base + t + j, b, bi);
        }
        __syncthreads();
    }

    const long o = ((long)chunk * N_Q + qid) * KNN;
#pragma unroll
    for (int k = 0; k < KNN; ++k) {
        g_part_d[o + k] = b[k];
        g_part_i[o + k] = bi[k];
    }
}

// ---------------------------------------------------------------------------
// Merge the SPLIT partial lists, compute IDW weights, gather flow, write out.
// POWER=2 => weight = 1 / (d^2 + eps); d^2 = max(d' + |q|^2, 0). No sqrt.
// ---------------------------------------------------------------------------
__global__ void merge_kernel(const float* __restrict__ q,
                             const float* __restrict__ flow,
                             float* __restrict__ out) {
    int qid = blockIdx.x * blockDim.x + threadIdx.x;
    if (qid >= N_Q) return;

    float b[KNN];
    int   bi[KNN];
#pragma unroll
    for (int k = 0; k < KNN; ++k) { b[k] = __int_as_float(0x7f800000); bi[k] = 0; }

    for (int s = 0; s < SPLIT; ++s) {          // ascending split order keeps
        const long o = ((long)s * N_Q + qid) * KNN;  // tie-order = ascending index
#pragma unroll
        for (int k = 0; k < KNN; ++k) {
            float d = g_part_d[o + k];
            int  id = g_part_i[o + k];
            if (d < b[7]) insert8(d, id, b, bi);
        }
    }

    const float qx = q[3 * qid + 0];
    const float qy = q[3 * qid + 1];
    const float qz = q[3 * qid + 2];
    const float q2 = qx * qx + qy * qy + qz * qz;

    float wsum = 0.0f, ax = 0.0f, ay = 0.0f, az = 0.0f;
#pragma unroll
    for (int k = 0; k < KNN; ++k) {
        float d2 = fmaxf(b[k] + q2, 0.0f);
        float w  = 1.0f / (d2 + 1e-8f);
        int  id  = bi[k];
        wsum += w;
        ax = fmaf(w, flow[3 * id + 0], ax);
        ay = fmaf(w, flow[3 * id + 1], ay);
        az = fmaf(w, flow[3 * id + 2], az);
    }
    const float inv = 1.0f / wsum;
    out[3 * qid + 0] = ax * inv;
    out[3 * qid + 1] = ay * inv;
    out[3 * qid + 2] = az * inv;
}

// ---------------------------------------------------------------------------
extern "C" void kernel_launch(void* const* d_in, const int* in_sizes, int n_in,
                              void* d_out, int out_size) {
    const float* q    = (const float*)d_in[0];   // query_points [N,3]
    const float* r    = (const float*)d_in[1];   // ref_points   [M,3]
    const float* f    = (const float*)d_in[2];   // ref_flow     [M,3]
    float*       out  = (float*)d_out;           // [N,3]

    prep_kernel<<<(M_R + 255) / 256, 256>>>(r);

    dim3 grid(N_Q / BQ, SPLIT);
    knn_kernel<<<grid, BQ>>>(q);

    merge_kernel<<<(N_Q + 255) / 256, 256>>>(q, f, out);
}